// round 17
// baseline (speedup 1.0000x reference)
#include <cuda_runtime.h>
#include <cuda_bf16.h>
#include <cuda_fp16.h>
#include <stdint.h>
#include <math.h>

#define BATCH   8
#define SEQ     4096
#define DIMN    512
#define HEADS   8
#define DHEAD   64
#define WIN     128
#define NW      (SEQ / WIN)
#define NTOK    (BATCH * SEQ)
#define QKVD    (3 * DIMN)
#define FFD     (4 * DIMN)

#define WSCALE     512.0f            // weights pre-scaled by 512 (exact pow2)
#define WSCALE_INV (1.0f / 512.0f)

// ======================= scratch (static device memory) ========================
__device__ float  g_qkv [(size_t)NTOK * QKVD];
__device__ float  g_x1  [(size_t)NTOK * DIMN];
__device__ __half g_h   [(size_t)NTOK * DIMN];
__device__ __half g_at  [(size_t)NTOK * DIMN];
__device__ __half g_f1  [(size_t)NTOK * FFD];
__device__ __half g_wqkv[QKVD * DIMN];
__device__ __half g_wout[DIMN * DIMN];
__device__ __half g_wff1[FFD * DIMN];
__device__ __half g_wff2[DIMN * FFD];
__device__ float  g_rotc[SEQ * 32];   // rotary cos table [pos][pair]
__device__ float  g_rots[SEQ * 32];   // rotary sin table

// ============================ helpers ==========================================
__device__ __forceinline__ uint32_t smem_u32(const void* p) {
    uint32_t a;
    asm("{ .reg .u64 t; cvta.to.shared.u64 t, %1; cvt.u32.u64 %0, t; }" : "=r"(a) : "l"(p));
    return a;
}
#define SWZ(o) ((o) ^ (((o) >> 3) & 0x70))   // SW128 swizzle, 128B rows

__device__ __forceinline__ void cp_async16(uint32_t dst, const void* src) {
    asm volatile("cp.async.cg.shared.global [%0], [%1], 16;" :: "r"(dst), "l"(src));
}
__device__ __forceinline__ void cp_commit() {
    asm volatile("cp.async.commit_group;");
}
template <int N>
__device__ __forceinline__ void cp_wait() {
    asm volatile("cp.async.wait_group %0;" :: "n"(N));
}
__device__ __forceinline__ void ldmatrix_x4(uint32_t& r0, uint32_t& r1,
                                            uint32_t& r2, uint32_t& r3, uint32_t a) {
    asm volatile("ldmatrix.sync.aligned.m8n8.x4.shared.b16 {%0,%1,%2,%3}, [%4];"
                 : "=r"(r0), "=r"(r1), "=r"(r2), "=r"(r3) : "r"(a));
}
__device__ __forceinline__ void mma_fp16(float* c, const uint32_t* a, const uint32_t* b) {
    asm volatile("mma.sync.aligned.m16n8k16.row.col.f32.f16.f16.f32 "
                 "{%0,%1,%2,%3}, {%4,%5,%6,%7}, {%8,%9}, {%0,%1,%2,%3};"
                 : "+f"(c[0]), "+f"(c[1]), "+f"(c[2]), "+f"(c[3])
                 : "r"(a[0]), "r"(a[1]), "r"(a[2]), "r"(a[3]), "r"(b[0]), "r"(b[1]));
}

// ---- packed fp32x2 (Blackwell): 2 IEEE fp32 ops per instruction ----
__device__ __forceinline__ unsigned long long ffma2(unsigned long long a,
                                                    unsigned long long b,
                                                    unsigned long long c) {
    unsigned long long d;
    asm("fma.rn.f32x2 %0, %1, %2, %3;" : "=l"(d) : "l"(a), "l"(b), "l"(c));
    return d;
}
__device__ __forceinline__ unsigned long long addf2(unsigned long long a,
                                                    unsigned long long b) {
    unsigned long long d;
    asm("add.rn.f32x2 %0, %1, %2;" : "=l"(d) : "l"(a), "l"(b));
    return d;
}
__device__ __forceinline__ float2 unpack2(unsigned long long v) {
    float2 r;
    asm("mov.b64 {%0, %1}, %2;" : "=f"(r.x), "=f"(r.y) : "l"(v));
    return r;
}
__device__ __forceinline__ unsigned long long pack2(float x, float y) {
    unsigned long long v;
    asm("mov.b64 %0, {%1, %2};" : "=l"(v) : "f"(x), "f"(y));
    return v;
}

// ================= LayerNorm -> fp16. block = token =============================
__global__ __launch_bounds__(128) void ln_kernel(const float* __restrict__ in,
                                                 const float* __restrict__ gamma,
                                                 const float* __restrict__ beta,
                                                 __half* __restrict__ oh)
{
    int t = blockIdx.x;
    int tid = threadIdx.x;
    const float4* row = (const float4*)(in + (size_t)t * DIMN);
    float4 v = row[tid];
    float s  = v.x + v.y + v.z + v.w;
    float ss = v.x * v.x + v.y * v.y + v.z * v.z + v.w * v.w;
#pragma unroll
    for (int o = 16; o > 0; o >>= 1) {
        s  += __shfl_xor_sync(0xffffffffu, s, o);
        ss += __shfl_xor_sync(0xffffffffu, ss, o);
    }
    __shared__ float sm[4], sm2[4];
    int w = tid >> 5, lane = tid & 31;
    if (lane == 0) { sm[w] = s; sm2[w] = ss; }
    __syncthreads();
    s  = sm[0] + sm[1] + sm[2] + sm[3];
    ss = sm2[0] + sm2[1] + sm2[2] + sm2[3];
    float mean = s * (1.0f / DIMN);
    float var  = ss * (1.0f / DIMN) - mean * mean;
    float inv  = rsqrtf(var + 1e-5f);
    float4 g = ((const float4*)gamma)[tid];
    float4 b = ((const float4*)beta)[tid];
    float o0 = (v.x - mean) * inv * g.x + b.x;
    float o1 = (v.y - mean) * inv * g.y + b.y;
    float o2 = (v.z - mean) * inv * g.z + b.z;
    float o3 = (v.w - mean) * inv * g.w + b.w;
    __half2 p0 = __floats2half2_rn(o0, o1);
    __half2 p1 = __floats2half2_rn(o2, o3);
    *(uint2*)(oh + (size_t)t * DIMN + tid * 4) = make_uint2(*(uint32_t*)&p0, *(uint32_t*)&p1);
}

// ====== merged weight convert: all 4 weights in one launch (512*w -> fp16) =====
__global__ void wconv4_kernel(const float* __restrict__ w0, __half* __restrict__ o0, int n0,
                              const float* __restrict__ w1, __half* __restrict__ o1, int n1,
                              const float* __restrict__ w2, __half* __restrict__ o2, int n2,
                              const float* __restrict__ w3, __half* __restrict__ o3, int n3)
{
    int i = blockIdx.x * blockDim.x + threadIdx.x;   // float4 granule index
    const float* in;
    __half* out;
    int j;
    if (i < n0)                 { in = w0; out = o0; j = i; }
    else if (i < n0 + n1)       { in = w1; out = o1; j = i - n0; }
    else if (i < n0 + n1 + n2)  { in = w2; out = o2; j = i - n0 - n1; }
    else if (i < n0 + n1 + n2 + n3) { in = w3; out = o3; j = i - n0 - n1 - n2; }
    else return;
    float4 v = ((const float4*)in)[j];
    __half2 p0 = __floats2half2_rn(v.x * WSCALE, v.y * WSCALE);
    __half2 p1 = __floats2half2_rn(v.z * WSCALE, v.w * WSCALE);
    ((uint2*)out)[j] = make_uint2(*(uint32_t*)&p0, *(uint32_t*)&p1);
}

// ========= rotary table: cos/sin of fp32 phase, exact double trig ===============
__global__ void rotary_kernel(float* __restrict__ rc, float* __restrict__ rs)
{
    int idx = blockIdx.x * blockDim.x + threadIdx.x;   // SEQ*32
    int n = idx >> 5, lane = idx & 31;
    double invf_d = exp(-(double)(2 * lane) * (9.210340371976184 / 64.0));
    float ph = (float)n * (float)invf_d;               // fp32 phase (matches ref)
    double sd, cd;
    sincos((double)ph, &sd, &cd);
    rc[idx] = (float)cd;
    rs[idx] = (float)sd;
}

// ====== local-window attention (R13 verbatim): f32x2, fixed-offset softmax =====
__global__ __launch_bounds__(128) void attn_kernel(const float* __restrict__ qkv,
                                                   __half* __restrict__ oh)
{
    __shared__ float sK[64][DHEAD];
    __shared__ float sV[64][DHEAD];

    int w = blockIdx.x, h = blockIdx.y, b = blockIdx.z;
    int i = threadIdx.x;
    int tok0 = b * SEQ + w * WIN;
    int tok  = tok0 + i;

    unsigned long long q2[32];   // 64 dims as 32 packed fp32 pairs
    {
        const ulonglong2* srcQ = (const ulonglong2*)(qkv + (size_t)tok * QKVD + h * DHEAD);
#pragma unroll
        for (int d = 0; d < 16; ++d) {
            ulonglong2 t2 = srcQ[d];
            q2[2 * d] = t2.x; q2[2 * d + 1] = t2.y;
        }
    }

    unsigned long long acc2[32];
#pragma unroll
    for (int d = 0; d < 32; ++d) acc2[d] = 0ull;
    float l = 0.f;

#pragma unroll 1
    for (int c = 0; c < 4; ++c) {
        if (c < 2 && w == 0) continue;

        __syncthreads();
        {
            int r  = i >> 1;
            int f0 = (i & 1) * 8;
            int ktok = tok0 + c * 64 - WIN + r;
            const float4* sk = (const float4*)(qkv + (size_t)ktok * QKVD + DIMN + h * DHEAD);
            const float4* sv = (const float4*)(qkv + (size_t)ktok * QKVD + 2 * DIMN + h * DHEAD);
            float4* dK = (float4*)&sK[r][0];
            float4* dV = (float4*)&sV[r][0];
#pragma unroll
            for (int f = 0; f < 8; ++f) { dK[f0 + f] = sk[f0 + f]; dV[f0 + f] = sv[f0 + f]; }
        }
        __syncthreads();

        int jmax;
        if (c < 2) jmax = 64;
        else {
            jmax = i - (c - 2) * 64 + 1;
            jmax = jmax < 0 ? 0 : (jmax > 64 ? 64 : jmax);
        }
        for (int j = 0; j < jmax; ++j) {
            const ulonglong2* kr = (const ulonglong2*)&sK[j][0];
            unsigned long long s0 = 0ull, s1 = 0ull, s2 = 0ull, s3 = 0ull;
#pragma unroll
            for (int d = 0; d < 16; ++d) {
                ulonglong2 kk = kr[d];
                if (d & 1) {
                    s2 = ffma2(q2[2 * d],     kk.x, s2);
                    s3 = ffma2(q2[2 * d + 1], kk.y, s3);
                } else {
                    s0 = ffma2(q2[2 * d],     kk.x, s0);
                    s1 = ffma2(q2[2 * d + 1], kk.y, s1);
                }
            }
            unsigned long long tsum = addf2(addf2(s0, s1), addf2(s2, s3));
            float2 tf = unpack2(tsum);
            float sc = (tf.x + tf.y) * 8.0f;   // QK_SCALE; |sc|<=8 (l2-normed q,k)
            float p  = __expf(sc);             // no overflow; offset-free softmax
            l += p;
            unsigned long long pp = pack2(p, p);
            const ulonglong2* vr = (const ulonglong2*)&sV[j][0];
#pragma unroll
            for (int d = 0; d < 16; ++d) {
                ulonglong2 vv = vr[d];
                acc2[2 * d]     = ffma2(pp, vv.x, acc2[2 * d]);
                acc2[2 * d + 1] = ffma2(pp, vv.y, acc2[2 * d + 1]);
            }
        }
    }

    float invl = 1.0f / l;
    size_t dstoff = (size_t)tok * DIMN + h * DHEAD;
#pragma unroll
    for (int g = 0; g < 8; ++g) {
        uint32_t hp[4];
#pragma unroll
        for (int k = 0; k < 4; ++k) {
            float2 f = unpack2(acc2[g * 4 + k]);
            __half2 hh = __floats2half2_rn(f.x * invl, f.y * invl);
            hp[k] = *(uint32_t*)&hh;
        }
        *(uint4*)(oh + dstoff + g * 8) = make_uint4(hp[0], hp[1], hp[2], hp[3]);
    }
}

// ====== HMMA GEMM fp16, double-buffered cp.async, 2 CTAs/SM ====================
// TN = 128: 4 M-warps x 2 N-warps (R16 config). TN = 64: 8 M-warps x 1 N-warp
//   (128x64 tiles) for N=512 GEMMs -> 2048 CTAs = 6.92 waves (vs 3.46) to kill
//   the 13.5% wave-tail loss.
// EPI: 0 fp32 | 1 +bias+resid fp32 | 2 gelu->fp16 | 3 +resid fp32
//      4 qkv epilogue: fused l2norm*scale + rotary for Q/K regions (TN=128).
#define KBLK     64

__device__ __forceinline__ float gelu_f(float x)
{
    return 0.5f * x * (1.0f + erff(x * 0.7071067811865476f));
}

template <int EPI, int TN>
__global__ __launch_bounds__(256, 2) void gemm_tc(
    const __half* __restrict__ A, const __half* __restrict__ B,
    int M, int N, int K,
    float* __restrict__ Cf, __half* __restrict__ Ch,
    const float* __restrict__ bias, const float* __restrict__ resid,
    const float* __restrict__ scq, const float* __restrict__ sck,
    const float* __restrict__ rc,  const float* __restrict__ rs)
{
    constexpr int NWM = (TN == 128) ? 4 : 8;        // M-warps
    constexpr int MI  = (TN == 128) ? 2 : 1;        // 16-row tiles per warp
    constexpr uint32_t ATILE = 16384;               // 128 rows x 128 B
    constexpr uint32_t BTILE = (uint32_t)TN * 128;  // TN rows x 128 B
    constexpr uint32_t STAGE = ATILE + BTILE;
    constexpr int BIT = (TN * 8) / 256;             // B granules per thread

    extern __shared__ char smem[];
    uint32_t sb = smem_u32(smem);
    int tid = threadIdx.x, wid = tid >> 5, lane = tid & 31;
    int warpM = wid % NWM, warpN = wid / NWM;
    int bm = blockIdx.y * 128, bn = blockIdx.x * TN;

    float acc[MI][8][4];
#pragma unroll
    for (int mi = 0; mi < MI; ++mi)
#pragma unroll
        for (int ni = 0; ni < 8; ++ni)
#pragma unroll
            for (int r = 0; r < 4; ++r) acc[mi][ni][r] = 0.f;

    int aRow  = lane & 15;
    int aKoff = (lane >> 4) << 3;
    int bRow  = (lane & 7) + ((lane >> 4) << 3);
    int bKoff = ((lane >> 3) & 1) << 3;

    int ldRow = tid >> 3, ldC16 = tid & 7;

    int kchunks = K / KBLK;

    // prologue: chunk 0 -> stage 0
    {
#pragma unroll
        for (int it = 0; it < 4; ++it) {
            int row = ldRow + it * 32;
            cp_async16(sb + SWZ(row * 128 + ldC16 * 16),
                       A + (size_t)(bm + row) * K + ldC16 * 8);
        }
#pragma unroll
        for (int it = 0; it < BIT; ++it) {
            int row = ldRow + it * 32;
            cp_async16(sb + ATILE + SWZ(row * 128 + ldC16 * 16),
                       B + (size_t)(bn + row) * K + ldC16 * 8);
        }
        cp_commit();
    }

#pragma unroll 1
    for (int kc = 0; kc < kchunks; ++kc) {
        uint32_t cur = sb + (uint32_t)(kc & 1) * STAGE;
        if (kc + 1 < kchunks) {
            uint32_t nxt = sb + (uint32_t)((kc + 1) & 1) * STAGE;
            int k0 = (kc + 1) * KBLK;
#pragma unroll
            for (int it = 0; it < 4; ++it) {
                int row = ldRow + it * 32;
                cp_async16(nxt + SWZ(row * 128 + ldC16 * 16),
                           A + (size_t)(bm + row) * K + k0 + ldC16 * 8);
            }
#pragma unroll
            for (int it = 0; it < BIT; ++it) {
                int row = ldRow + it * 32;
                cp_async16(nxt + ATILE + SWZ(row * 128 + ldC16 * 16),
                           B + (size_t)(bn + row) * K + k0 + ldC16 * 8);
            }
            cp_commit();
            cp_wait<1>();
        } else {
            cp_wait<0>();
        }
        __syncthreads();

#pragma unroll
        for (int k16 = 0; k16 < KBLK / 16; ++k16) {
            uint32_t a[MI][4], b[8][2];
#pragma unroll
            for (int mi = 0; mi < MI; ++mi) {
                uint32_t ao = SWZ((warpM * (MI * 16) + mi * 16 + aRow) * 128 +
                                  (k16 * 16 + aKoff) * 2);
                ldmatrix_x4(a[mi][0], a[mi][1], a[mi][2], a[mi][3], cur + ao);
            }
#pragma unroll
            for (int np = 0; np < 4; ++np) {
                uint32_t bo = SWZ((warpN * 64 + np * 16 + bRow) * 128 +
                                  (k16 * 16 + bKoff) * 2);
                ldmatrix_x4(b[np * 2][0], b[np * 2][1],
                            b[np * 2 + 1][0], b[np * 2 + 1][1], cur + ATILE + bo);
            }
#pragma unroll
            for (int mi = 0; mi < MI; ++mi)
#pragma unroll
                for (int ni = 0; ni < 8; ++ni)
                    mma_fp16(acc[mi][ni], a[mi], b[ni]);
        }
        __syncthreads();
    }

    if (EPI == 4) {
        // whole 128-col tile inside one 512-aligned region (Q, K, or V)
        const float* sc = (bn < DIMN) ? scq : (bn < 2 * DIMN ? sck : nullptr);
#pragma unroll
        for (int mi = 0; mi < MI; ++mi)
#pragma unroll
            for (int hh = 0; hh < 2; ++hh) {
                int r = bm + warpM * (MI * 16) + mi * 16 + (lane >> 2) + hh * 8;
                float v0[8], v1[8];
#pragma unroll
                for (int ni = 0; ni < 8; ++ni) {
                    v0[ni] = acc[mi][ni][hh * 2 + 0] * WSCALE_INV;
                    v1[ni] = acc[mi][ni][hh * 2 + 1] * WSCALE_INV;
                }
                if (sc) {   // uniform per CTA
                    float ssq = 0.f;
#pragma unroll
                    for (int ni = 0; ni < 8; ++ni)
                        ssq += v0[ni] * v0[ni] + v1[ni] * v1[ni];
                    ssq += __shfl_xor_sync(0xffffffffu, ssq, 1);
                    ssq += __shfl_xor_sync(0xffffffffu, ssq, 2);
                    float inv = 1.0f / fmaxf(sqrtf(ssq), 1e-12f);
                    int n = r & (SEQ - 1);
                    int off = (lane & 3) * 2;
#pragma unroll
                    for (int ni = 0; ni < 4; ++ni) {
                        int d = ni * 8 + off;                 // d in [0,31)
                        float c0 = rc[n * 32 + d],     s0 = rs[n * 32 + d];
                        float c1 = rc[n * 32 + d + 1], s1 = rs[n * 32 + d + 1];
                        float lo0 = v0[ni]     * inv * sc[d];
                        float hi0 = v0[ni + 4] * inv * sc[d + 32];
                        float lo1 = v1[ni]     * inv * sc[d + 1];
                        float hi1 = v1[ni + 4] * inv * sc[d + 33];
                        v0[ni]     = lo0 * c0 - hi0 * s0;
                        v0[ni + 4] = hi0 * c0 + lo0 * s0;
                        v1[ni]     = lo1 * c1 - hi1 * s1;
                        v1[ni + 4] = hi1 * c1 + lo1 * s1;
                    }
                }
#pragma unroll
                for (int ni = 0; ni < 8; ++ni) {
                    int col = bn + warpN * 64 + ni * 8 + (lane & 3) * 2;
                    *(float2*)(Cf + (size_t)r * N + col) = make_float2(v0[ni], v1[ni]);
                }
            }
        return;
    }

#pragma unroll
    for (int mi = 0; mi < MI; ++mi)
#pragma unroll
        for (int ni = 0; ni < 8; ++ni) {
            int row = bm + warpM * (MI * 16) + mi * 16 + (lane >> 2);
            int col = bn + warpN * 64 + ni * 8 + (lane & 3) * 2;
#pragma unroll
            for (int hh = 0; hh < 2; ++hh) {
                int r = row + hh * 8;
                float v0 = acc[mi][ni][hh * 2 + 0] * WSCALE_INV;
                float v1 = acc[mi][ni][hh * 2 + 1] * WSCALE_INV;
                size_t idx = (size_t)r * N + col;
                if (EPI == 2) {
                    __half2 hp = __floats2half2_rn(gelu_f(v0), gelu_f(v1));
                    *(uint32_t*)(Ch + idx) = *(uint32_t*)&hp;
                } else {
                    if (EPI == 1) {
                        float2 rs2 = *(const float2*)(resid + idx);
                        v0 += bias[col] + rs2.x;
                        v1 += bias[col + 1] + rs2.y;
                    } else if (EPI == 3) {
                        float2 rs2 = *(const float2*)(resid + idx);
                        v0 += rs2.x; v1 += rs2.y;
                    }
                    *(float2*)(Cf + idx) = make_float2(v0, v1);
                }
            }
        }
}

// ------------------------------- launch ---------------------------------------
extern "C" void kernel_launch(void* const* d_in, const int* in_sizes, int n_in,
                              void* d_out, int out_size)
{
    const float* x       = (const float*)d_in[0];
    const float* w_qkv   = (const float*)d_in[1];
    const float* q_scale = (const float*)d_in[2];
    const float* k_scale = (const float*)d_in[3];
    const float* w_out   = (const float*)d_in[4];
    const float* b_out   = (const float*)d_in[5];
    const float* ln1_g   = (const float*)d_in[6];
    const float* ln1_b   = (const float*)d_in[7];
    const float* ff_ln_g = (const float*)d_in[8];
    const float* ff_ln_b = (const float*)d_in[9];
    const float* w_ff1   = (const float*)d_in[10];
    const float* w_ff2   = (const float*)d_in[11];
    float* out = (float*)d_out;

    float *p_qkv, *p_x1, *p_rotc, *p_rots;
    __half *p_h, *p_at, *p_f1, *p_wqkv, *p_wout, *p_wff1, *p_wff2;
    cudaGetSymbolAddress((void**)&p_qkv, g_qkv);
    cudaGetSymbolAddress((void**)&p_x1, g_x1);
    cudaGetSymbolAddress((void**)&p_rotc, g_rotc);
    cudaGetSymbolAddress((void**)&p_rots, g_rots);
    cudaGetSymbolAddress((void**)&p_h, g_h);
    cudaGetSymbolAddress((void**)&p_at, g_at);
    cudaGetSymbolAddress((void**)&p_f1, g_f1);
    cudaGetSymbolAddress((void**)&p_wqkv, g_wqkv);
    cudaGetSymbolAddress((void**)&p_wout, g_wout);
    cudaGetSymbolAddress((void**)&p_wff1, g_wff1);
    cudaGetSymbolAddress((void**)&p_wff2, g_wff2);

    const int SM128 = 2 * (16384 + 128 * 128);   // 64 KB (TN=128)
    const int SM64  = 2 * (16384 + 64 * 128);    // 48 KB (TN=64)
    cudaFuncSetAttribute((gemm_tc<4, 128>), cudaFuncAttributeMaxDynamicSharedMemorySize, SM128);
    cudaFuncSetAttribute((gemm_tc<2, 128>), cudaFuncAttributeMaxDynamicSharedMemorySize, SM128);
    cudaFuncSetAttribute((gemm_tc<1, 64>),  cudaFuncAttributeMaxDynamicSharedMemorySize, SM64);
    cudaFuncSetAttribute((gemm_tc<3, 64>),  cudaFuncAttributeMaxDynamicSharedMemorySize, SM64);

    // rotary table + merged weight converts
    rotary_kernel<<<(SEQ * 32) / 256, 256>>>(p_rotc, p_rots);
    {
        int n0 = QKVD * DIMN / 4, n1 = DIMN * DIMN / 4;
        int n2 = FFD * DIMN / 4,  n3 = DIMN * FFD / 4;
        int ntot = n0 + n1 + n2 + n3;
        wconv4_kernel<<<(ntot + 255) / 256, 256>>>(w_qkv, p_wqkv, n0,
                                                   w_out, p_wout, n1,
                                                   w_ff1, p_wff1, n2,
                                                   w_ff2, p_wff2, n3);
    }

    // 1) h = LN1(x) -> fp16
    ln_kernel<<<NTOK, 128>>>(x, ln1_g, ln1_b, p_h);

    // 2) qkv = h @ w_qkv^T with FUSED q/k l2norm*scale+rotary epilogue
    gemm_tc<4, 128><<<dim3(QKVD / 128, NTOK / 128), 256, SM128>>>(
        p_h, p_wqkv, NTOK, QKVD, DIMN, p_qkv, nullptr, nullptr, nullptr,
        q_scale, k_scale, p_rotc, p_rots);

    // 3) attention -> fp16
    attn_kernel<<<dim3(NW, HEADS, BATCH), 128>>>(p_qkv, p_at);

    // 4) x1 = x + attn @ w_out^T + b_out   (TN=64: 6.92 waves)
    gemm_tc<1, 64><<<dim3(DIMN / 64, NTOK / 128), 256, SM64>>>(
        p_at, p_wout, NTOK, DIMN, DIMN, p_x1, nullptr, b_out, x,
        nullptr, nullptr, nullptr, nullptr);

    // 5) h = LN2(x1) -> fp16
    ln_kernel<<<NTOK, 128>>>(p_x1, ff_ln_g, ff_ln_b, p_h);

    // 6) ff1 = gelu(h @ w_ff1^T) -> fp16
    gemm_tc<2, 128><<<dim3(FFD / 128, NTOK / 128), 256, SM128>>>(
        p_h, p_wff1, NTOK, FFD, DIMN, nullptr, p_f1, nullptr, nullptr,
        nullptr, nullptr, nullptr, nullptr);

    // 7) out = x1 + ff1 @ w_ff2^T   (TN=64: 6.92 waves)
    gemm_tc<3, 64><<<dim3(DIMN / 64, NTOK / 128), 256, SM64>>>(
        p_f1, p_wff2, NTOK, DIMN, FFD, out, nullptr, nullptr, p_x1,
        nullptr, nullptr, nullptr, nullptr);
}